// round 9
// baseline (speedup 1.0000x reference)
#include <cuda_runtime.h>
#include <cuda_bf16.h>
#include <cstdint>
#include <math.h>

#define NPTS 50000
#define KNB  16
#define HALF 64
#define DIM  128
#define TILES8 (NPTS / 8)        // 6250
#define RS    272                // smem row stride bytes (136 bf16: 128 + 8 pad)

// ---------------- scratch (__device__ globals; no allocs allowed) -------
__device__ float g_p0[NPTS * HALF];
__device__ float g_p1[NPTS * HALF];
__device__ float g_u [NPTS * DIM];   // p1 @ W3a_top
__device__ float g_cc[NPTS * DIM];   // b3a - u + p_local @ W3a_bot

// grid barrier state (generation-based; resets naturally every call)
__device__ unsigned int g_barCnt = 0;
__device__ volatile unsigned int g_barGen = 0;

// ---------------- smem map (bytes) ----------------
// Phase A: sW2 [0,16384)  sp0 [16384,17408)
// Phase B: sW3a [0,65536) sp1 [65536,+4096) spl(+4096) sb(+512) sknn(+1024)
// Phase C: WB_HI 0 (34816), WB_LO 34816, BB 69632 (512)
#define OFF_WB_HI 0
#define OFF_WB_LO 34816
#define OFF_BB    69632
#define PB_SP1    65536
#define PB_SPL    (PB_SP1 + 4096)
#define PB_SB     (PB_SPL + 4096)
#define PB_SKNN   (PB_SB + 512)
#define SMEM_BYTES 76288

// ---------------- low-level helpers ----------------
static __device__ __forceinline__ uint32_t smem_to_u32(const void* p) {
    uint32_t a;
    asm("{ .reg .u64 t; cvta.to.shared.u64 t, %1; cvt.u32.u64 %0, t; }" : "=r"(a) : "l"(p));
    return a;
}
static __device__ __forceinline__ void ldsm_x4(uint32_t* r, uint32_t addr) {
    asm volatile("ldmatrix.sync.aligned.m8n8.x4.shared.b16 {%0,%1,%2,%3}, [%4];"
        : "=r"(r[0]), "=r"(r[1]), "=r"(r[2]), "=r"(r[3]) : "r"(addr));
}
static __device__ __forceinline__ void mma16816(float* d, const uint32_t* a, const uint32_t* b) {
    asm volatile("mma.sync.aligned.m16n8k16.row.col.f32.bf16.bf16.f32 "
        "{%0,%1,%2,%3}, {%4,%5,%6,%7}, {%8,%9}, {%0,%1,%2,%3};"
        : "+f"(d[0]), "+f"(d[1]), "+f"(d[2]), "+f"(d[3])
        : "r"(a[0]), "r"(a[1]), "r"(a[2]), "r"(a[3]), "r"(b[0]), "r"(b[1]));
}
static __device__ __forceinline__ float gelu_exact(float x) {
    return 0.5f * x * (1.0f + erff(x * 0.70710678118654752f));
}
static __device__ __forceinline__ uint32_t split_trunc2(float a, float b, float &ra, float &rb) {
    uint32_t ua = __float_as_uint(a) & 0xFFFF0000u;
    uint32_t ub = __float_as_uint(b) & 0xFFFF0000u;
    ra = a - __uint_as_float(ua);
    rb = b - __uint_as_float(ub);
    return __byte_perm(ua, ub, 0x7632);
}
static __device__ __forceinline__ uint32_t cvt_bf2(float a, float b) {   // x=a, y=b
    uint32_t r;
    asm("cvt.rn.bf16x2.f32 %0, %1, %2;" : "=r"(r) : "f"(b), "f"(a));
    return r;
}
static __device__ __forceinline__ uint32_t split_rn2(float a, float b, float &ra, float &rb) {
    __nv_bfloat16 ha = __float2bfloat16_rn(a), hb = __float2bfloat16_rn(b);
    ra = a - __bfloat162float(ha);
    rb = b - __bfloat162float(hb);
    __nv_bfloat162 p; p.x = ha; p.y = hb;
    return *(uint32_t*)&p;
}
static __host__ __device__ __forceinline__ int perm_pair(int k) {
    int b = k & ~15, r = k & 15;
    return b + ((r >> 2) << 1) + ((r & 2) << 2);
}
// L2-coherent loads for data produced earlier in this kernel
static __device__ __forceinline__ float4 ldcg_f4(const float* p) {
    float4 v;
    asm volatile("ld.global.cg.v4.f32 {%0,%1,%2,%3}, [%4];"
        : "=f"(v.x), "=f"(v.y), "=f"(v.z), "=f"(v.w) : "l"(p));
    return v;
}
static __device__ __forceinline__ float ldcg_f(const float* p) {
    float v;
    asm volatile("ld.global.cg.f32 %0, [%1];" : "=f"(v) : "l"(p));
    return v;
}

// two-phase generation grid barrier (all CTAs co-resident by construction)
static __device__ __forceinline__ void grid_sync() {
    __syncthreads();
    if (threadIdx.x == 0) {
        __threadfence();
        unsigned int gen = g_barGen;
        if (atomicAdd(&g_barCnt, 1u) == gridDim.x - 1u) {
            g_barCnt = 0;
            __threadfence();
            g_barGen = gen + 1u;
        } else {
            while (g_barGen == gen) __nanosleep(64);
        }
        __threadfence();
    }
    __syncthreads();
}

// ---------------- the fused persistent kernel ----------------
__global__ void __launch_bounds__(256, 2)
k_fused(const float* __restrict__ xyz, const int* __restrict__ knn,
        const float* __restrict__ W1, const float* __restrict__ b1,
        const float* __restrict__ W2, const float* __restrict__ b2,
        const float* __restrict__ W3a, const float* __restrict__ b3a,
        const float* __restrict__ W3b, const float* __restrict__ b3b,
        float* __restrict__ out) {
    extern __shared__ char smem[];
    const uint32_t sbase = smem_to_u32(smem);
    const int tid  = threadIdx.x;
    const int wid  = tid >> 5;
    const int lane = tid & 31;

    // ================= Phase A: p0 = xyz@W1+b1 ; p1 = p0@W2+b2 =========
    {
        float* sW2 = (float*)smem;                 // 64x64
        float* sp0 = (float*)(smem + 16384);       // 4x64
        for (int t = tid; t < HALF * HALF; t += 256) sW2[t] = __ldg(&W2[t]);
        __syncthreads();

        const int lp = tid >> 6;
        const int c  = tid & 63;
        for (int unit = blockIdx.x; unit < NPTS / 4; unit += gridDim.x) {
            const int i = unit * 4 + lp;
            float x = __ldg(&xyz[i * 3 + 0]);
            float y = __ldg(&xyz[i * 3 + 1]);
            float z = __ldg(&xyz[i * 3 + 2]);
            float v = fmaf(z, __ldg(&W1[2 * HALF + c]), __ldg(&b1[c]));
            v = fmaf(y, __ldg(&W1[1 * HALF + c]), v);
            v = fmaf(x, __ldg(&W1[0 * HALF + c]), v);
            g_p0[i * HALF + c] = v;
            sp0[lp * HALF + c] = v;
            __syncthreads();

            float acc = __ldg(&b2[c]);
#pragma unroll
            for (int e = 0; e < HALF; e++)
                acc = fmaf(sp0[lp * HALF + e], sW2[e * HALF + c], acc);
            g_p1[i * HALF + c] = acc;
            __syncthreads();   // protect sp0 before next unit
        }
    }
    grid_sync();

    // ================= Phase B: p_local ; u = p1@Wtop ; cc ==============
    {
        float* sW   = (float*)smem;                // 128x128 W3a
        float* sp1  = (float*)(smem + PB_SP1);     // 16x64
        float* spl  = (float*)(smem + PB_SPL);     // 16x64
        float* sb   = (float*)(smem + PB_SB);      // 128
        int*   sknn = (int*)(smem + PB_SKNN);      // 256

        for (int t = tid; t < DIM * DIM; t += 256) sW[t] = __ldg(&W3a[t]);
        if (tid < 128) sb[tid] = __ldg(&b3a[tid]);
        __syncthreads();

        for (int unit = blockIdx.x; unit < NPTS / 16; unit += gridDim.x) {
            const int base = unit * 16;
            sknn[tid] = __ldg(&knn[base * KNB + tid]);
            for (int t = tid; t < 1024; t += 256) {
                int p = t >> 6, e = t & 63;
                sp1[t] = ldcg_f(&g_p1[(base + p) * HALF + e]);
            }
            __syncthreads();

            // p_local = max_k (p0[knn] - p0)
            for (int t = tid; t < 1024; t += 256) {
                int p = t >> 6, c = t & 63;
                float own = ldcg_f(&g_p0[(base + p) * HALF + c]);
                float m = -3.402823466e38f;
#pragma unroll
                for (int k = 0; k < KNB; k++) {
                    int j = sknn[p * KNB + k];
                    m = fmaxf(m, ldcg_f(&g_p0[j * HALF + c]) - own);
                }
                spl[t] = m;
            }
            __syncthreads();

            // u / cc
            const int c  = tid & 127;
            const int ph = (tid >> 7) * 8;
            float aU[8], aC[8];
#pragma unroll
            for (int pp = 0; pp < 8; pp++) { aU[pp] = 0.f; aC[pp] = sb[c]; }
#pragma unroll 8
            for (int e = 0; e < HALF; e++) {
                float w1 = sW[e * DIM + c];
                float w2 = sW[(HALF + e) * DIM + c];
#pragma unroll
                for (int pp = 0; pp < 8; pp++) {
                    aU[pp] = fmaf(sp1[(ph + pp) * HALF + e], w1, aU[pp]);
                    aC[pp] = fmaf(spl[(ph + pp) * HALF + e], w2, aC[pp]);
                }
            }
#pragma unroll
            for (int pp = 0; pp < 8; pp++) {
                size_t idx = (size_t)(base + ph + pp) * DIM + c;
                g_u[idx]  = aU[pp];
                g_cc[idx] = aC[pp] - aU[pp];
            }
            __syncthreads();   // protect sp1/spl/sknn before next unit
        }
    }
    grid_sync();

    // ================= Phase C: gather+GELU -> GEMM2 ====================
    {
        float* sBb = (float*)(smem + OFF_BB);

        // build k-permuted split W3b in smem
        for (int idx = tid; idx < 8192; idx += 256) {
            int n = idx >> 6, ep = idx & 63, k = ep << 1;
            uint32_t off = (uint32_t)n * RS + (uint32_t)perm_pair(k) * 2;
            float b0 = __ldg(&W3b[k * DIM + n]);
            float b1v = __ldg(&W3b[(k + 1) * DIM + n]);
            float rb0, rb1;
            *(uint32_t*)(smem + OFF_WB_HI + off) = split_rn2(b0, b1v, rb0, rb1);
            *(uint32_t*)(smem + OFF_WB_LO + off) = cvt_bf2(rb0, rb1);
        }
        if (tid < 128) sBb[tid] = __ldg(&b3b[tid]);
        __syncthreads();

        const int qr = lane >> 2;
        const int qc = (lane & 3) * 2;
        const int q4 = (lane & 3) * 4;
        const uint32_t bOff = ((uint32_t)(lane & 7) + ((uint32_t)(lane >> 4) & 1) * 8) * RS
                            + ((uint32_t)(lane >> 3) & 1) * 16;
        const uint32_t wHi = sbase + OFF_WB_HI + bOff;
        const uint32_t wLo = sbase + OFF_WB_LO + bOff;

        const int gstep = gridDim.x;
        int tile = blockIdx.x;
        int jj = (tile < TILES8) ? __ldg(&knn[(tile * 8 + wid) * KNB + (lane & 15)]) : 0;

        for (; tile < TILES8; tile += gstep) {
            const int i = tile * 8 + wid;

            const int tnext = tile + gstep;
            int jjn = 0;
            if (tnext < TILES8) jjn = __ldg(&knn[(tnext * 8 + wid) * KNB + (lane & 15)]);

            const int j0 = __shfl_sync(0xFFFFFFFF, jj, qr);
            const int j1 = __shfl_sync(0xFFFFFFFF, jj, qr + 8);

            const float* u0 = g_u  + (size_t)j0 * DIM + q4;
            const float* u1 = g_u  + (size_t)j1 * DIM + q4;
            const float* cp = g_cc + (size_t)i  * DIM + q4;

            float acc[16][4];
#pragma unroll
            for (int t = 0; t < 16; t++) { acc[t][0] = acc[t][1] = acc[t][2] = acc[t][3] = 0.f; }

            float4 va = ldcg_f4(u0);
            float4 vb = ldcg_f4(u1);
            float4 vc = ldcg_f4(cp);

#pragma unroll
            for (int ks = 0; ks < 8; ks++) {
                float4 na, nb, nc;
                if (ks < 7) {
                    const int kb = (ks + 1) * 16;
                    na = ldcg_f4(u0 + kb);
                    nb = ldcg_f4(u1 + kb);
                    nc = ldcg_f4(cp + kb);
                }
                float h00 = gelu_exact(va.x + vc.x), h01 = gelu_exact(va.y + vc.y);
                float h02 = gelu_exact(va.z + vc.z), h03 = gelu_exact(va.w + vc.w);
                float h10 = gelu_exact(vb.x + vc.x), h11 = gelu_exact(vb.y + vc.y);
                float h12 = gelu_exact(vb.z + vc.z), h13 = gelu_exact(vb.w + vc.w);

                uint32_t aHi[4], aLo[4];
                float r0, r1, r2, r3;
                aHi[0] = split_trunc2(h00, h01, r0, r1);
                aHi[2] = split_trunc2(h02, h03, r2, r3);
                aLo[0] = cvt_bf2(r0, r1);
                aLo[2] = cvt_bf2(r2, r3);
                aHi[1] = split_trunc2(h10, h11, r0, r1);
                aHi[3] = split_trunc2(h12, h13, r2, r3);
                aLo[1] = cvt_bf2(r0, r1);
                aLo[3] = cvt_bf2(r2, r3);

                const uint32_t ka = (uint32_t)ks * 32;
#pragma unroll
                for (int ntp = 0; ntp < 8; ntp++) {
                    uint32_t bHi[4], bLo[4];
                    ldsm_x4(bHi, wHi + (uint32_t)ntp * 16 * RS + ka);
                    ldsm_x4(bLo, wLo + (uint32_t)ntp * 16 * RS + ka);
                    mma16816(acc[2 * ntp],     aHi, bHi);
                    mma16816(acc[2 * ntp + 1], aHi, bHi + 2);
                    mma16816(acc[2 * ntp],     aHi, bLo);
                    mma16816(acc[2 * ntp + 1], aHi, bLo + 2);
                    mma16816(acc[2 * ntp],     aLo, bHi);
                    mma16816(acc[2 * ntp + 1], aLo, bHi + 2);
                }
                va = na; vb = nb; vc = nc;
            }

            // epilogue: +b3b, store
            {
                float* obase = out + ((size_t)i * KNB) * DIM;
#pragma unroll
                for (int nt = 0; nt < 16; nt++) {
                    int c = nt * 8 + qc;
                    float bb0 = sBb[c], bb1 = sBb[c + 1];
                    *(float2*)(obase + (size_t)qr * DIM + c) =
                        make_float2(acc[nt][0] + bb0, acc[nt][1] + bb1);
                    *(float2*)(obase + (size_t)(qr + 8) * DIM + c) =
                        make_float2(acc[nt][2] + bb0, acc[nt][3] + bb1);
                }
            }
            jj = jjn;
        }
    }
}

// ---------------- launch ----------------
extern "C" void kernel_launch(void* const* d_in, const int* in_sizes, int n_in,
                              void* d_out, int out_size) {
    const float* xyz = (const float*)d_in[0];
    const int*   knn = (const int*)d_in[1];
    const float* W1  = (const float*)d_in[2];
    const float* b1  = (const float*)d_in[3];
    const float* W2  = (const float*)d_in[4];
    const float* b2  = (const float*)d_in[5];
    const float* W3a = (const float*)d_in[6];
    const float* b3a = (const float*)d_in[7];
    const float* W3b = (const float*)d_in[8];
    const float* b3b = (const float*)d_in[9];
    float* out = (float*)d_out;

    cudaFuncSetAttribute(k_fused, cudaFuncAttributeMaxDynamicSharedMemorySize, SMEM_BYTES);

    int dev = 0, sms = 148;
    cudaGetDevice(&dev);
    cudaDeviceGetAttribute(&sms, cudaDevAttrMultiProcessorCount, dev);
    int maxB = 1;
    cudaOccupancyMaxActiveBlocksPerMultiprocessor(&maxB, k_fused, 256, SMEM_BYTES);
    if (maxB < 1) maxB = 1;
    if (maxB > 2) maxB = 2;
    const int grid = sms * maxB;   // all CTAs co-resident -> grid barrier safe

    k_fused<<<grid, 256, SMEM_BYTES>>>(xyz, knn, W1, b1, W2, b2,
                                       W3a, b3a, W3b, b3b, out);
}

// round 10
// speedup vs baseline: 1.0839x; 1.0839x over previous
#include <cuda_runtime.h>
#include <cuda_bf16.h>
#include <cstdint>
#include <math.h>

#define NPTS 50000
#define KNB  16
#define HALF 64
#define DIM  128
#define TILES8 (NPTS / 8)        // 6250
#define RS    272                // smem row stride bytes (136 bf16: 128 + 8 pad)

// ---------------- scratch (__device__ globals; no allocs allowed) -------
__device__ float g_p0[NPTS * HALF];
__device__ float g_p1[NPTS * HALF];
__device__ float g_u [NPTS * DIM];   // p1 @ W3a_top
__device__ float g_cc[NPTS * DIM];   // b3a - u + p_local @ W3a_bot

// ---------------- k_mlp smem map (bytes) ----------------
#define OFF_WB_HI 0
#define OFF_WB_LO 34816
#define OFF_BB    69632
#define SMEM_BYTES 70144

// k_uc smem: 16384 W + 1024 p1 + 1024 pl + 128 b + 256 knn = 18816 floats
#define UC_SMEM_BYTES 75264

// ---------------- helpers ----------------
static __device__ __forceinline__ uint32_t smem_to_u32(const void* p) {
    uint32_t a;
    asm("{ .reg .u64 t; cvta.to.shared.u64 t, %1; cvt.u32.u64 %0, t; }" : "=r"(a) : "l"(p));
    return a;
}
static __device__ __forceinline__ void ldsm_x4(uint32_t* r, uint32_t addr) {
    asm volatile("ldmatrix.sync.aligned.m8n8.x4.shared.b16 {%0,%1,%2,%3}, [%4];"
        : "=r"(r[0]), "=r"(r[1]), "=r"(r[2]), "=r"(r[3]) : "r"(addr));
}
static __device__ __forceinline__ void mma16816(float* d, const uint32_t* a, const uint32_t* b) {
    asm volatile("mma.sync.aligned.m16n8k16.row.col.f32.bf16.bf16.f32 "
        "{%0,%1,%2,%3}, {%4,%5,%6,%7}, {%8,%9}, {%0,%1,%2,%3};"
        : "+f"(d[0]), "+f"(d[1]), "+f"(d[2]), "+f"(d[3])
        : "r"(a[0]), "r"(a[1]), "r"(a[2]), "r"(a[3]), "r"(b[0]), "r"(b[1]));
}
// branch-free gelu via A&S 7.1.26 erfc (|eps| <= 1.5e-7), 2 MUFU
static __device__ __forceinline__ float gelu_fast(float x) {
    const float za = fabsf(x) * 0.70710678118654752f;
    float den = fmaf(za, 0.3275911f, 1.0f);
    float t;
    asm("rcp.approx.f32 %0, %1;" : "=f"(t) : "f"(den));
    // halved A&S coefficients -> E = 0.5*erfc(|z|)
    float q = t * fmaf(t, fmaf(t, fmaf(t, fmaf(t, 0.5307027145f, -0.7265760135f),
                                       0.7107068705f), -0.142248368f), 0.127414796f);
    float ex;
    asm("ex2.approx.f32 %0, %1;" : "=f"(ex) : "f"(za * za * -1.442695041f));
    float E  = q * ex;           // 0.5*erfc(|x|/sqrt2)
    float xe = x * E;
    return (x >= 0.f) ? (x - xe) : xe;
}
static __device__ __forceinline__ uint32_t split_trunc2(float a, float b, float &ra, float &rb) {
    uint32_t ua = __float_as_uint(a) & 0xFFFF0000u;
    uint32_t ub = __float_as_uint(b) & 0xFFFF0000u;
    ra = a - __uint_as_float(ua);
    rb = b - __uint_as_float(ub);
    return __byte_perm(ua, ub, 0x7632);
}
static __device__ __forceinline__ uint32_t cvt_bf2(float a, float b) {   // x=a, y=b
    uint32_t r;
    asm("cvt.rn.bf16x2.f32 %0, %1, %2;" : "=r"(r) : "f"(b), "f"(a));
    return r;
}
static __device__ __forceinline__ uint32_t split_rn2(float a, float b, float &ra, float &rb) {
    __nv_bfloat16 ha = __float2bfloat16_rn(a), hb = __float2bfloat16_rn(b);
    ra = a - __bfloat162float(ha);
    rb = b - __bfloat162float(hb);
    __nv_bfloat162 p; p.x = ha; p.y = hb;
    return *(uint32_t*)&p;
}
static __host__ __device__ __forceinline__ int perm_pair(int k) {
    int b = k & ~15, r = k & 15;
    return b + ((r >> 2) << 1) + ((r & 2) << 2);
}

// ---------------- kernel 1: p0 = xyz@W1+b1 ; p1 = p0@W2+b2 ----------------
// 16 points/block; phase-2 threads each compute 4 points for one column so
// every W2 load is reused 4x (k_p01 was L1-LDG bound).
__global__ void __launch_bounds__(256)
k_p01(const float* __restrict__ xyz, const float* __restrict__ W1,
      const float* __restrict__ b1, const float* __restrict__ W2,
      const float* __restrict__ b2) {
    __shared__ float sp0[16][HALF];
    const int tid  = threadIdx.x;
    const int base = blockIdx.x * 16;

    for (int t = tid; t < 16 * HALF; t += 256) {
        int p = t >> 6, c = t & 63;
        int i = base + p;
        float x = __ldg(&xyz[i * 3 + 0]);
        float y = __ldg(&xyz[i * 3 + 1]);
        float z = __ldg(&xyz[i * 3 + 2]);
        float v = fmaf(z, __ldg(&W1[2 * HALF + c]), __ldg(&b1[c]));
        v = fmaf(y, __ldg(&W1[1 * HALF + c]), v);
        v = fmaf(x, __ldg(&W1[0 * HALF + c]), v);
        g_p0[i * HALF + c] = v;
        sp0[p][c] = v;
    }
    __syncthreads();

    const int c  = tid & 63;
    const int p0i = (tid >> 6) * 4;      // this thread's 4 points
    float bb = __ldg(&b2[c]);
    float a0 = bb, a1 = bb, a2 = bb, a3 = bb;
#pragma unroll 8
    for (int e = 0; e < HALF; e++) {
        float w = __ldg(&W2[e * HALF + c]);
        a0 = fmaf(sp0[p0i + 0][e], w, a0);
        a1 = fmaf(sp0[p0i + 1][e], w, a1);
        a2 = fmaf(sp0[p0i + 2][e], w, a2);
        a3 = fmaf(sp0[p0i + 3][e], w, a3);
    }
    g_p1[(base + p0i + 0) * HALF + c] = a0;
    g_p1[(base + p0i + 1) * HALF + c] = a1;
    g_p1[(base + p0i + 2) * HALF + c] = a2;
    g_p1[(base + p0i + 3) * HALF + c] = a3;
}

// ---------------- kernel 2: fused p_local + (u, cc) --------------------
__global__ void __launch_bounds__(256)
k_uc(const int* __restrict__ knn, const float* __restrict__ W3a,
     const float* __restrict__ b3a) {
    extern __shared__ float us[];
    float* sW   = us;              // 16384
    float* sp1  = us + 16384;      // 16 x 64
    float* spl  = sp1 + 1024;      // 16 x 64
    float* sb   = spl + 1024;      // 128
    int*   sknn = (int*)(sb + 128);// 256

    const int tid  = threadIdx.x;
    const int base = blockIdx.x * 16;

    for (int t = tid; t < 16384; t += 256) sW[t] = __ldg(&W3a[t]);
    if (tid < 128) sb[tid] = __ldg(&b3a[tid]);
    sknn[tid] = __ldg(&knn[base * KNB + tid]);
    for (int t = tid; t < 1024; t += 256) {
        int p = t >> 6, e = t & 63;
        sp1[t] = g_p1[(base + p) * HALF + e];
    }
    __syncthreads();

    // p_local = max_k (p0[knn] - p0)
    for (int t = tid; t < 1024; t += 256) {
        int p = t >> 6, c = t & 63;
        float own = g_p0[(base + p) * HALF + c];
        float m = -3.402823466e38f;
#pragma unroll
        for (int k = 0; k < KNB; k++) {
            int j = sknn[p * KNB + k];
            m = fmaxf(m, __ldg(&g_p0[j * HALF + c]) - own);
        }
        spl[t] = m;
    }
    __syncthreads();

    // u / cc
    const int c  = tid & 127;
    const int ph = (tid >> 7) * 8;
    float aU[8], aC[8];
#pragma unroll
    for (int pp = 0; pp < 8; pp++) { aU[pp] = 0.f; aC[pp] = sb[c]; }
#pragma unroll 8
    for (int e = 0; e < HALF; e++) {
        float w1 = sW[e * DIM + c];
        float w2 = sW[(HALF + e) * DIM + c];
#pragma unroll
        for (int pp = 0; pp < 8; pp++) {
            aU[pp] = fmaf(sp1[(ph + pp) * HALF + e], w1, aU[pp]);
            aC[pp] = fmaf(spl[(ph + pp) * HALF + e], w2, aC[pp]);
        }
    }
#pragma unroll
    for (int pp = 0; pp < 8; pp++) {
        size_t idx = (size_t)(base + ph + pp) * DIM + c;
        g_u[idx]  = aU[pp];
        g_cc[idx] = aC[pp] - aU[pp];
    }
}

// ---------------- kernel 3: register-direct gather+GELU -> GEMM2 ---------
__global__ void __launch_bounds__(256, 2)
k_mlp(const int* __restrict__ knn,
      const float* __restrict__ W3b, const float* __restrict__ b3b,
      float* __restrict__ out) {
    extern __shared__ char smem[];
    const uint32_t sbase = smem_to_u32(smem);
    const int tid  = threadIdx.x;
    const int wid  = tid >> 5;
    const int lane = tid & 31;

    float* sBb = (float*)(smem + OFF_BB);

    // ---- load + split W3b: stored [n][perm(k)] = W[k][n], bf16 hi/lo ----
    for (int idx = tid; idx < 8192; idx += 256) {
        int n = idx >> 6, ep = idx & 63, k = ep << 1;
        uint32_t off = (uint32_t)n * RS + (uint32_t)perm_pair(k) * 2;
        float b0 = __ldg(&W3b[k * DIM + n]);
        float b1v = __ldg(&W3b[(k + 1) * DIM + n]);
        float rb0, rb1;
        *(uint32_t*)(smem + OFF_WB_HI + off) = split_rn2(b0, b1v, rb0, rb1);
        *(uint32_t*)(smem + OFF_WB_LO + off) = cvt_bf2(rb0, rb1);
    }
    if (tid < 128) sBb[tid] = __ldg(&b3b[tid]);
    __syncthreads();

    const int qr = lane >> 2;
    const int qc = (lane & 3) * 2;
    const int q4 = (lane & 3) * 4;
    const uint32_t bOff = ((uint32_t)(lane & 7) + ((uint32_t)(lane >> 4) & 1) * 8) * RS
                        + ((uint32_t)(lane >> 3) & 1) * 16;
    const uint32_t wHi = sbase + OFF_WB_HI + bOff;
    const uint32_t wLo = sbase + OFF_WB_LO + bOff;

    const int gstep = gridDim.x;
    int tile = blockIdx.x;
    int jj = (tile < TILES8) ? __ldg(&knn[(tile * 8 + wid) * KNB + (lane & 15)]) : 0;

    for (; tile < TILES8; tile += gstep) {
        const int i = tile * 8 + wid;

        const int tnext = tile + gstep;
        int jjn = 0;
        if (tnext < TILES8) jjn = __ldg(&knn[(tnext * 8 + wid) * KNB + (lane & 15)]);

        const int j0 = __shfl_sync(0xFFFFFFFF, jj, qr);
        const int j1 = __shfl_sync(0xFFFFFFFF, jj, qr + 8);

        const float* u0 = g_u  + (size_t)j0 * DIM + q4;
        const float* u1 = g_u  + (size_t)j1 * DIM + q4;
        const float* cp = g_cc + (size_t)i  * DIM + q4;

        float acc[16][4];
#pragma unroll
        for (int t = 0; t < 16; t++) { acc[t][0] = acc[t][1] = acc[t][2] = acc[t][3] = 0.f; }

        float4 va = *(const float4*)(u0);
        float4 vb = *(const float4*)(u1);
        float4 vc = *(const float4*)(cp);

#pragma unroll
        for (int ks = 0; ks < 8; ks++) {
            float4 na, nb, nc;
            if (ks < 7) {
                const int kb = (ks + 1) * 16;
                na = *(const float4*)(u0 + kb);
                nb = *(const float4*)(u1 + kb);
                nc = *(const float4*)(cp + kb);
            }
            float h00 = gelu_fast(va.x + vc.x), h01 = gelu_fast(va.y + vc.y);
            float h02 = gelu_fast(va.z + vc.z), h03 = gelu_fast(va.w + vc.w);
            float h10 = gelu_fast(vb.x + vc.x), h11 = gelu_fast(vb.y + vc.y);
            float h12 = gelu_fast(vb.z + vc.z), h13 = gelu_fast(vb.w + vc.w);

            uint32_t aHi[4], aLo[4];
            float r0, r1, r2, r3;
            aHi[0] = split_trunc2(h00, h01, r0, r1);
            aHi[2] = split_trunc2(h02, h03, r2, r3);
            aLo[0] = cvt_bf2(r0, r1);
            aLo[2] = cvt_bf2(r2, r3);
            aHi[1] = split_trunc2(h10, h11, r0, r1);
            aHi[3] = split_trunc2(h12, h13, r2, r3);
            aLo[1] = cvt_bf2(r0, r1);
            aLo[3] = cvt_bf2(r2, r3);

            const uint32_t ka = (uint32_t)ks * 32;
#pragma unroll
            for (int ntp = 0; ntp < 8; ntp++) {
                uint32_t bHi[4], bLo[4];
                ldsm_x4(bHi, wHi + (uint32_t)ntp * 16 * RS + ka);
                ldsm_x4(bLo, wLo + (uint32_t)ntp * 16 * RS + ka);
                mma16816(acc[2 * ntp],     aHi, bHi);
                mma16816(acc[2 * ntp + 1], aHi, bHi + 2);
                mma16816(acc[2 * ntp],     aHi, bLo);
                mma16816(acc[2 * ntp + 1], aHi, bLo + 2);
                mma16816(acc[2 * ntp],     aLo, bHi);
                mma16816(acc[2 * ntp + 1], aLo, bHi + 2);
            }
            va = na; vb = nb; vc = nc;
        }

        // ---- epilogue: +b3b, store ----
        {
            float* obase = out + ((size_t)i * KNB) * DIM;
#pragma unroll
            for (int nt = 0; nt < 16; nt++) {
                int c = nt * 8 + qc;
                float bb0 = sBb[c], bb1 = sBb[c + 1];
                *(float2*)(obase + (size_t)qr * DIM + c) =
                    make_float2(acc[nt][0] + bb0, acc[nt][1] + bb1);
                *(float2*)(obase + (size_t)(qr + 8) * DIM + c) =
                    make_float2(acc[nt][2] + bb0, acc[nt][3] + bb1);
            }
        }
        jj = jjn;
    }
}

// ---------------- launch ----------------
extern "C" void kernel_launch(void* const* d_in, const int* in_sizes, int n_in,
                              void* d_out, int out_size) {
    const float* xyz = (const float*)d_in[0];
    const int*   knn = (const int*)d_in[1];
    const float* W1  = (const float*)d_in[2];
    const float* b1  = (const float*)d_in[3];
    const float* W2  = (const float*)d_in[4];
    const float* b2  = (const float*)d_in[5];
    const float* W3a = (const float*)d_in[6];
    const float* b3a = (const float*)d_in[7];
    const float* W3b = (const float*)d_in[8];
    const float* b3b = (const float*)d_in[9];
    float* out = (float*)d_out;

    k_p01<<<NPTS / 16, 256>>>(xyz, W1, b1, W2, b2);

    cudaFuncSetAttribute(k_uc, cudaFuncAttributeMaxDynamicSharedMemorySize, UC_SMEM_BYTES);
    k_uc<<<NPTS / 16, 256, UC_SMEM_BYTES>>>(knn, W3a, b3a);

    cudaFuncSetAttribute(k_mlp, cudaFuncAttributeMaxDynamicSharedMemorySize, SMEM_BYTES);
    int dev = 0, sms = 148;
    cudaGetDevice(&dev);
    cudaDeviceGetAttribute(&sms, cudaDevAttrMultiProcessorCount, dev);
    k_mlp<<<2 * sms, 256, SMEM_BYTES>>>(knn, W3b, b3b, out);
}

// round 11
// speedup vs baseline: 1.1046x; 1.0191x over previous
#include <cuda_runtime.h>
#include <cuda_bf16.h>
#include <cstdint>
#include <math.h>

#define NPTS 50000
#define KNB  16
#define HALF 64
#define DIM  128
#define TILES8 (NPTS / 8)        // 6250
#define RS    272                // smem row stride bytes (136 bf16: 128 + 8 pad)

// ---------------- scratch (__device__ globals; no allocs allowed) -------
__device__ float g_p0[NPTS * HALF];
__device__ float g_p1[NPTS * HALF];
__device__ float g_u [NPTS * DIM];   // p1 @ W3a_top
__device__ float g_cc[NPTS * DIM];   // b3a - u + p_local @ W3a_bot

// ---------------- k_mlp smem map (bytes) ----------------
#define OFF_WB_HI 0
#define OFF_WB_LO 34816
#define OFF_BB    69632
#define SMEM_BYTES 70144

#define UC_SMEM_BYTES 75264

// ---------------- helpers ----------------
static __device__ __forceinline__ uint32_t smem_to_u32(const void* p) {
    uint32_t a;
    asm("{ .reg .u64 t; cvta.to.shared.u64 t, %1; cvt.u32.u64 %0, t; }" : "=r"(a) : "l"(p));
    return a;
}
static __device__ __forceinline__ void ldsm_x4(uint32_t* r, uint32_t addr) {
    asm volatile("ldmatrix.sync.aligned.m8n8.x4.shared.b16 {%0,%1,%2,%3}, [%4];"
        : "=r"(r[0]), "=r"(r[1]), "=r"(r[2]), "=r"(r[3]) : "r"(addr));
}
static __device__ __forceinline__ void mma16816(float* d, const uint32_t* a, const uint32_t* b) {
    asm volatile("mma.sync.aligned.m16n8k16.row.col.f32.bf16.bf16.f32 "
        "{%0,%1,%2,%3}, {%4,%5,%6,%7}, {%8,%9}, {%0,%1,%2,%3};"
        : "+f"(d[0]), "+f"(d[1]), "+f"(d[2]), "+f"(d[3])
        : "r"(a[0]), "r"(a[1]), "r"(a[2]), "r"(a[3]), "r"(b[0]), "r"(b[1]));
}
// branch-free gelu via A&S 7.1.26 erfc (|eps| <= 1.5e-7), 2 MUFU
static __device__ __forceinline__ float gelu_fast(float x) {
    const float za = fabsf(x) * 0.70710678118654752f;
    float den = fmaf(za, 0.3275911f, 1.0f);
    float t;
    asm("rcp.approx.f32 %0, %1;" : "=f"(t) : "f"(den));
    float q = t * fmaf(t, fmaf(t, fmaf(t, fmaf(t, 0.5307027145f, -0.7265760135f),
                                       0.7107068705f), -0.142248368f), 0.127414796f);
    float ex;
    asm("ex2.approx.f32 %0, %1;" : "=f"(ex) : "f"(za * za * -1.442695041f));
    float E  = q * ex;
    float xe = x * E;
    return (x >= 0.f) ? (x - xe) : xe;
}
static __device__ __forceinline__ uint32_t split_trunc2(float a, float b, float &ra, float &rb) {
    uint32_t ua = __float_as_uint(a) & 0xFFFF0000u;
    uint32_t ub = __float_as_uint(b) & 0xFFFF0000u;
    ra = a - __uint_as_float(ua);
    rb = b - __uint_as_float(ub);
    return __byte_perm(ua, ub, 0x7632);
}
static __device__ __forceinline__ uint32_t cvt_bf2(float a, float b) {   // x=a, y=b
    uint32_t r;
    asm("cvt.rn.bf16x2.f32 %0, %1, %2;" : "=r"(r) : "f"(b), "f"(a));
    return r;
}
static __device__ __forceinline__ uint32_t split_rn2(float a, float b, float &ra, float &rb) {
    __nv_bfloat16 ha = __float2bfloat16_rn(a), hb = __float2bfloat16_rn(b);
    ra = a - __bfloat162float(ha);
    rb = b - __bfloat162float(hb);
    __nv_bfloat162 p; p.x = ha; p.y = hb;
    return *(uint32_t*)&p;
}
static __host__ __device__ __forceinline__ int perm_pair(int k) {
    int b = k & ~15, r = k & 15;
    return b + ((r >> 2) << 1) + ((r & 2) << 2);
}

// ---------------- kernel 1: p0 = xyz@W1+b1 ; p1 = p0@W2+b2 ----------------
__global__ void __launch_bounds__(256)
k_p01(const float* __restrict__ xyz, const float* __restrict__ W1,
      const float* __restrict__ b1, const float* __restrict__ W2,
      const float* __restrict__ b2) {
    __shared__ float sp0[16][HALF];
    const int tid  = threadIdx.x;
    const int base = blockIdx.x * 16;

    for (int t = tid; t < 16 * HALF; t += 256) {
        int p = t >> 6, c = t & 63;
        int i = base + p;
        float x = __ldg(&xyz[i * 3 + 0]);
        float y = __ldg(&xyz[i * 3 + 1]);
        float z = __ldg(&xyz[i * 3 + 2]);
        float v = fmaf(z, __ldg(&W1[2 * HALF + c]), __ldg(&b1[c]));
        v = fmaf(y, __ldg(&W1[1 * HALF + c]), v);
        v = fmaf(x, __ldg(&W1[0 * HALF + c]), v);
        g_p0[i * HALF + c] = v;
        sp0[p][c] = v;
    }
    __syncthreads();

    const int c  = tid & 63;
    const int p0i = (tid >> 6) * 4;
    float bb = __ldg(&b2[c]);
    float a0 = bb, a1 = bb, a2 = bb, a3 = bb;
#pragma unroll 8
    for (int e = 0; e < HALF; e++) {
        float w = __ldg(&W2[e * HALF + c]);
        a0 = fmaf(sp0[p0i + 0][e], w, a0);
        a1 = fmaf(sp0[p0i + 1][e], w, a1);
        a2 = fmaf(sp0[p0i + 2][e], w, a2);
        a3 = fmaf(sp0[p0i + 3][e], w, a3);
    }
    g_p1[(base + p0i + 0) * HALF + c] = a0;
    g_p1[(base + p0i + 1) * HALF + c] = a1;
    g_p1[(base + p0i + 2) * HALF + c] = a2;
    g_p1[(base + p0i + 3) * HALF + c] = a3;
}

// ---------------- kernel 2: fused p_local + (u, cc) --------------------
__global__ void __launch_bounds__(256)
k_uc(const int* __restrict__ knn, const float* __restrict__ W3a,
     const float* __restrict__ b3a) {
    extern __shared__ float us[];
    float* sW   = us;              // 16384
    float* sp1  = us + 16384;      // 16 x 64
    float* spl  = sp1 + 1024;      // 16 x 64
    float* sb   = spl + 1024;      // 128
    int*   sknn = (int*)(sb + 128);// 256

    const int tid  = threadIdx.x;
    const int base = blockIdx.x * 16;

    for (int t = tid; t < 16384; t += 256) sW[t] = __ldg(&W3a[t]);
    if (tid < 128) sb[tid] = __ldg(&b3a[tid]);
    sknn[tid] = __ldg(&knn[base * KNB + tid]);
    for (int t = tid; t < 1024; t += 256) {
        int p = t >> 6, e = t & 63;
        sp1[t] = g_p1[(base + p) * HALF + e];
    }
    __syncthreads();

    for (int t = tid; t < 1024; t += 256) {
        int p = t >> 6, c = t & 63;
        float own = g_p0[(base + p) * HALF + c];
        float m = -3.402823466e38f;
#pragma unroll
        for (int k = 0; k < KNB; k++) {
            int j = sknn[p * KNB + k];
            m = fmaxf(m, __ldg(&g_p0[j * HALF + c]) - own);
        }
        spl[t] = m;
    }
    __syncthreads();

    const int c  = tid & 127;
    const int ph = (tid >> 7) * 8;
    float aU[8], aC[8];
#pragma unroll
    for (int pp = 0; pp < 8; pp++) { aU[pp] = 0.f; aC[pp] = sb[c]; }
#pragma unroll 8
    for (int e = 0; e < HALF; e++) {
        float w1 = sW[e * DIM + c];
        float w2 = sW[(HALF + e) * DIM + c];
#pragma unroll
        for (int pp = 0; pp < 8; pp++) {
            aU[pp] = fmaf(sp1[(ph + pp) * HALF + e], w1, aU[pp]);
            aC[pp] = fmaf(spl[(ph + pp) * HALF + e], w2, aC[pp]);
        }
    }
#pragma unroll
    for (int pp = 0; pp < 8; pp++) {
        size_t idx = (size_t)(base + ph + pp) * DIM + c;
        g_u[idx]  = aU[pp];
        g_cc[idx] = aC[pp] - aU[pp];
    }
}

// ---------------- kernel 3: cross-tile pipelined gather+GELU -> GEMM2 ----
__global__ void __launch_bounds__(256, 2)
k_mlp(const int* __restrict__ knn,
      const float* __restrict__ W3b, const float* __restrict__ b3b,
      float* __restrict__ out) {
    extern __shared__ char smem[];
    const uint32_t sbase = smem_to_u32(smem);
    const int tid  = threadIdx.x;
    const int wid  = tid >> 5;
    const int lane = tid & 31;

    float* sBb = (float*)(smem + OFF_BB);

    // ---- load + split W3b: stored [n][perm(k)] = W[k][n], bf16 hi/lo ----
    for (int idx = tid; idx < 8192; idx += 256) {
        int n = idx >> 6, ep = idx & 63, k = ep << 1;
        uint32_t off = (uint32_t)n * RS + (uint32_t)perm_pair(k) * 2;
        float b0 = __ldg(&W3b[k * DIM + n]);
        float b1v = __ldg(&W3b[(k + 1) * DIM + n]);
        float rb0, rb1;
        *(uint32_t*)(smem + OFF_WB_HI + off) = split_rn2(b0, b1v, rb0, rb1);
        *(uint32_t*)(smem + OFF_WB_LO + off) = cvt_bf2(rb0, rb1);
    }
    if (tid < 128) sBb[tid] = __ldg(&b3b[tid]);
    __syncthreads();

    const int qr = lane >> 2;
    const int qc = (lane & 3) * 2;
    const int q4 = (lane & 3) * 4;
    const uint32_t bOff = ((uint32_t)(lane & 7) + ((uint32_t)(lane >> 4) & 1) * 8) * RS
                        + ((uint32_t)(lane >> 3) & 1) * 16;
    const uint32_t wHi = sbase + OFF_WB_HI + bOff;
    const uint32_t wLo = sbase + OFF_WB_LO + bOff;

    const int gstep = gridDim.x;
    int tile = blockIdx.x;
    if (tile >= TILES8) return;

    // ---- prologue: indices + ks0 data for the first tile ----
    int jj = __ldg(&knn[(tile * 8 + wid) * KNB + (lane & 15)]);
    const float* u0;
    const float* u1;
    const float* cp;
    {
        const int j0 = __shfl_sync(0xFFFFFFFF, jj, qr);
        const int j1 = __shfl_sync(0xFFFFFFFF, jj, qr + 8);
        u0 = g_u  + (size_t)j0 * DIM + q4;
        u1 = g_u  + (size_t)j1 * DIM + q4;
        cp = g_cc + (size_t)(tile * 8 + wid) * DIM + q4;
    }
    float4 va = *(const float4*)(u0);
    float4 vb = *(const float4*)(u1);
    float4 vc = *(const float4*)(cp);

    for (; tile < TILES8; tile += gstep) {
        const int i = tile * 8 + wid;

        // prefetch next tile's neighbor indices (early, covers shuffle at ks==7)
        const int tnext = tile + gstep;
        int jjn = 0;
        if (tnext < TILES8) jjn = __ldg(&knn[(tnext * 8 + wid) * KNB + (lane & 15)]);

        float acc[16][4];
#pragma unroll
        for (int t = 0; t < 16; t++) { acc[t][0] = acc[t][1] = acc[t][2] = acc[t][3] = 0.f; }

#pragma unroll
        for (int ks = 0; ks < 8; ks++) {
            float4 na, nb, nc;
            if (ks < 7) {
                const int kb = (ks + 1) * 16;
                na = *(const float4*)(u0 + kb);
                nb = *(const float4*)(u1 + kb);
                nc = *(const float4*)(cp + kb);
            } else {
                // rebase to next tile's rows and issue its ks0 loads now;
                // the epilogue below covers their latency
                const int j0n = __shfl_sync(0xFFFFFFFF, jjn, qr);
                const int j1n = __shfl_sync(0xFFFFFFFF, jjn, qr + 8);
                const int inext = (tnext < TILES8) ? (tnext * 8 + wid) : 0;
                u0 = g_u  + (size_t)j0n * DIM + q4;
                u1 = g_u  + (size_t)j1n * DIM + q4;
                cp = g_cc + (size_t)inext * DIM + q4;
                na = *(const float4*)(u0);
                nb = *(const float4*)(u1);
                nc = *(const float4*)(cp);
            }

            float h00 = gelu_fast(va.x + vc.x), h01 = gelu_fast(va.y + vc.y);
            float h02 = gelu_fast(va.z + vc.z), h03 = gelu_fast(va.w + vc.w);
            float h10 = gelu_fast(vb.x + vc.x), h11 = gelu_fast(vb.y + vc.y);
            float h12 = gelu_fast(vb.z + vc.z), h13 = gelu_fast(vb.w + vc.w);

            uint32_t aHi[4], aLo[4];
            float r0, r1, r2, r3;
            aHi[0] = split_trunc2(h00, h01, r0, r1);
            aHi[2] = split_trunc2(h02, h03, r2, r3);
            aLo[0] = cvt_bf2(r0, r1);
            aLo[2] = cvt_bf2(r2, r3);
            aHi[1] = split_trunc2(h10, h11, r0, r1);
            aHi[3] = split_trunc2(h12, h13, r2, r3);
            aLo[1] = cvt_bf2(r0, r1);
            aLo[3] = cvt_bf2(r2, r3);

            const uint32_t ka = (uint32_t)ks * 32;
#pragma unroll
            for (int ntp = 0; ntp < 8; ntp++) {
                uint32_t bHi[4], bLo[4];
                ldsm_x4(bHi, wHi + (uint32_t)ntp * 16 * RS + ka);
                ldsm_x4(bLo, wLo + (uint32_t)ntp * 16 * RS + ka);
                mma16816(acc[2 * ntp],     aHi, bHi);
                mma16816(acc[2 * ntp + 1], aHi, bHi + 2);
                mma16816(acc[2 * ntp],     aHi, bLo);
                mma16816(acc[2 * ntp + 1], aHi, bLo + 2);
                mma16816(acc[2 * ntp],     aLo, bHi);
                mma16816(acc[2 * ntp + 1], aLo, bHi + 2);
            }
            va = na; vb = nb; vc = nc;
        }

        // ---- epilogue: +b3b, store (covers next tile's ks0 load latency) ----
        {
            float* obase = out + ((size_t)i * KNB) * DIM;
#pragma unroll
            for (int nt = 0; nt < 16; nt++) {
                int c = nt * 8 + qc;
                float bb0 = sBb[c], bb1 = sBb[c + 1];
                *(float2*)(obase + (size_t)qr * DIM + c) =
                    make_float2(acc[nt][0] + bb0, acc[nt][1] + bb1);
                *(float2*)(obase + (size_t)(qr + 8) * DIM + c) =
                    make_float2(acc[nt][2] + bb0, acc[nt][3] + bb1);
            }
        }
        jj = jjn;
    }
}

// ---------------- launch ----------------
extern "C" void kernel_launch(void* const* d_in, const int* in_sizes, int n_in,
                              void* d_out, int out_size) {
    const float* xyz = (const float*)d_in[0];
    const int*   knn = (const int*)d_in[1];
    const float* W1  = (const float*)d_in[2];
    const float* b1  = (const float*)d_in[3];
    const float* W2  = (const float*)d_in[4];
    const float* b2  = (const float*)d_in[5];
    const float* W3a = (const float*)d_in[6];
    const float* b3a = (const float*)d_in[7];
    const float* W3b = (const float*)d_in[8];
    const float* b3b = (const float*)d_in[9];
    float* out = (float*)d_out;

    k_p01<<<NPTS / 16, 256>>>(xyz, W1, b1, W2, b2);

    cudaFuncSetAttribute(k_uc, cudaFuncAttributeMaxDynamicSharedMemorySize, UC_SMEM_BYTES);
    k_uc<<<NPTS / 16, 256, UC_SMEM_BYTES>>>(knn, W3a, b3a);

    cudaFuncSetAttribute(k_mlp, cudaFuncAttributeMaxDynamicSharedMemorySize, SMEM_BYTES);
    int dev = 0, sms = 148;
    cudaGetDevice(&dev);
    cudaDeviceGetAttribute(&sms, cudaDevAttrMultiProcessorCount, dev);
    k_mlp<<<2 * sms, 256, SMEM_BYTES>>>(knn, W3b, b3b, out);
}